// round 9
// baseline (speedup 1.0000x reference)
#include <cuda_runtime.h>
#include <cuda_bf16.h>
#include <math.h>
#include <stdint.h>

// Problem constants
#define NN   100000
#define EE   3200000
#define INF  512
#define HF   256
#define OUTF 64
#define TOTE (EE + NN)

// ---------------- device scratch (no allocs allowed) ----------------
__device__ alignas(16) float g_bufA[(size_t)NN * HF];
__device__ alignas(16) float g_h  [(size_t)NN * OUTF];
__device__ float g_dinv[NN];
__device__ int   g_deg[NN];
__device__ int   g_cursor[NN];
__device__ int   g_rowptr[NN + 1];
__device__ alignas(16) int2 g_edge[TOTE];     // (col, norm-bits)
__device__ float g_stats[2 * HF];
__device__ int   g_bsum[512];
__device__ int   g_boff[512];

// quantized propagation buffers: 2x int16 per uint32 (2 features/lane) + row scale
__device__ alignas(16) uint32_t g_q1[(size_t)NN * 32];
__device__ alignas(16) uint32_t g_q2[(size_t)NN * 32];
__device__ float g_sc1[NN];
__device__ float g_sc2[NN];

// bf16 split operand buffers (hi/lo), max shape 100k x 512
__device__ alignas(16) __nv_bfloat16 g_ahi[(size_t)NN * INF];
__device__ alignas(16) __nv_bfloat16 g_alo[(size_t)NN * INF];
// weight operands [Nd, K] (K-major)
__device__ alignas(16) __nv_bfloat16 g_w1hi[HF * INF],  g_w1lo[HF * INF];
__device__ alignas(16) __nv_bfloat16 g_w2hi[HF * HF],   g_w2lo[HF * HF];
__device__ alignas(16) __nv_bfloat16 g_w3hi[HF * HF],   g_w3lo[HF * HF];
__device__ alignas(16) __nv_bfloat16 g_w4hi[OUTF * HF], g_w4lo[OUTF * HF];

__device__ __forceinline__ float gelu_exact(float x) {
    return 0.5f * x * (1.0f + erff(x * 0.70710678118654752f));
}

__device__ __forceinline__ uint32_t smem_u32(const void* p) {
    uint32_t a;
    asm("{ .reg .u64 t; cvta.to.shared.u64 t, %1; cvt.u32.u64 %0, t; }" : "=r"(a) : "l"(p));
    return a;
}

#define LDSM_X4(r0, r1, r2, r3, addr) \
    asm volatile("ldmatrix.sync.aligned.m8n8.x4.shared.b16 {%0,%1,%2,%3}, [%4];" \
        : "=r"(r0), "=r"(r1), "=r"(r2), "=r"(r3) : "r"(addr))

#define MMA_BF16(c, a0, a1, a2, a3, b0, b1) \
    asm volatile("mma.sync.aligned.m16n8k16.row.col.f32.bf16.bf16.f32 " \
        "{%0,%1,%2,%3}, {%4,%5,%6,%7}, {%8,%9}, {%0,%1,%2,%3};" \
        : "+f"((c)[0]), "+f"((c)[1]), "+f"((c)[2]), "+f"((c)[3]) \
        : "r"(a0), "r"(a1), "r"(a2), "r"(a3), "r"(b0), "r"(b1))

__device__ __forceinline__ void cp16(uint32_t s, const void* g, bool p) {
    asm volatile("cp.async.ca.shared.global [%0], [%1], 16, %2;"
                 :: "r"(s), "l"(g), "r"(p ? 16 : 0));
}
#define CP_COMMIT() asm volatile("cp.async.commit_group;" ::: "memory")
#define CP_WAIT1()  asm volatile("cp.async.wait_group 1;" ::: "memory")

// ---------------- graph preprocessing ----------------
__global__ void init_kernel() {
    int i = blockIdx.x * blockDim.x + threadIdx.x;
    if (i < NN) { g_deg[i] = 1; g_cursor[i] = 0; }
}
__global__ void degree_kernel(const int* __restrict__ row) {
    int e = blockIdx.x * blockDim.x + threadIdx.x;
    if (e < EE) atomicAdd(&g_deg[row[e]], 1);
}
__global__ void dinv_kernel() {
    int i = blockIdx.x * blockDim.x + threadIdx.x;
    if (i < NN) g_dinv[i] = rsqrtf((float)g_deg[i]);
}
__global__ void scan1_kernel() {
    __shared__ int sh[256];
    int t = threadIdx.x, i = blockIdx.x * 256 + t;
    int v = (i < NN) ? g_deg[i] : 0;
    sh[t] = v; __syncthreads();
    for (int o = 1; o < 256; o <<= 1) {
        int u = (t >= o) ? sh[t - o] : 0;
        __syncthreads(); sh[t] += u; __syncthreads();
    }
    if (i < NN) g_rowptr[i] = sh[t] - v;
    if (t == 255) g_bsum[blockIdx.x] = sh[255];
}
__global__ void scan2_kernel(int nb) {
    __shared__ int sh[512];
    int t = threadIdx.x;
    int v = (t < nb) ? g_bsum[t] : 0;
    sh[t] = v; __syncthreads();
    for (int o = 1; o < 512; o <<= 1) {
        int u = (t >= o) ? sh[t - o] : 0;
        __syncthreads(); sh[t] += u; __syncthreads();
    }
    g_boff[t] = sh[t] - v;
}
__global__ void scan3_kernel() {
    int i = blockIdx.x * 256 + threadIdx.x;
    if (i < NN) g_rowptr[i] += g_boff[blockIdx.x];
    if (i == 0) g_rowptr[NN] = TOTE;
}
__global__ void scatter_kernel(const int* __restrict__ row, const int* __restrict__ col) {
    int idx = blockIdx.x * blockDim.x + threadIdx.x;
    if (idx >= TOTE) return;
    int r, c;
    if (idx < EE) { r = row[idx]; c = col[idx]; }
    else          { r = idx - EE; c = r; }
    int pos = g_rowptr[r] + atomicAdd(&g_cursor[r], 1);
    g_edge[pos] = make_int2(c, __float_as_int(g_dinv[r] * g_dinv[c]));
}

// ---------------- fp32 -> bf16 hi/lo splits ----------------
__global__ void split2_kernel(const float* __restrict__ in,
                              __nv_bfloat162* __restrict__ hi,
                              __nv_bfloat162* __restrict__ lo, size_t n2) {
    size_t i = (size_t)blockIdx.x * blockDim.x + threadIdx.x;
    if (i >= n2) return;
    float2 v = ((const float2*)in)[i];
    __nv_bfloat16 hx = __float2bfloat16(v.x), hy = __float2bfloat16(v.y);
    __nv_bfloat16 lx = __float2bfloat16(v.x - __bfloat162float(hx));
    __nv_bfloat16 ly = __float2bfloat16(v.y - __bfloat162float(hy));
    hi[i] = __nv_bfloat162(hx, hy);
    lo[i] = __nv_bfloat162(lx, ly);
}
__global__ void wsplit_kernel(const float* __restrict__ w,
                              __nv_bfloat16* __restrict__ whi,
                              __nv_bfloat16* __restrict__ wlo, int K, int Nd) {
    int idx = blockIdx.x * blockDim.x + threadIdx.x;
    if (idx >= K * Nd) return;
    int k = idx / Nd, n = idx % Nd;
    float v = w[(size_t)k * Nd + n];
    __nv_bfloat16 h = __float2bfloat16(v);
    whi[(size_t)n * K + k] = h;
    wlo[(size_t)n * K + k] = __float2bfloat16(v - __bfloat162float(h));
}

// ---------------- HMMA split-bf16 GEMM (cp.async 2-stage) ----------------
// C[M,ND] = A[M,KK]*B[ND,KK]^T + bias. 3-pass: AhBh + AhBl + AlBh.
// Block: 128 rows x BLKN cols, BK=32, 8 warps (4M x 2N), warp tile 32 x BLKN/2.
template <int ND, int BLKN, int KK, bool STATS, bool FUSEH>
__global__ __launch_bounds__(256)
void hmma_gemm_kernel(const __nv_bfloat16* __restrict__ Ahi, const __nv_bfloat16* __restrict__ Alo,
                      const __nv_bfloat16* __restrict__ Bhi, const __nv_bfloat16* __restrict__ Blo,
                      const float* __restrict__ bias, float* __restrict__ C, int M,
                      float* __restrict__ outp, const float* __restrict__ alpha) {
    constexpr int LDS = 40;
    constexpr int WN  = BLKN / 2;          // warp N extent
    constexpr int NFR = WN / 8;            // 8-col fragments per warp
    constexpr int NP  = WN / 16;           // ldmatrix groups per warp
    constexpr int AH_OFF = 0;
    constexpr int AL_OFF = 128 * LDS * 2;
    constexpr int BH_OFF = AL_OFF + 128 * LDS * 2;
    constexpr int BL_OFF = BH_OFF + BLKN * LDS * 2;
    constexpr int STAGE  = BL_OFF + BLKN * LDS * 2;
    constexpr int NC = KK / 32;

    extern __shared__ __align__(16) char smem[];
    float* sSum = (float*)(smem + 2 * STAGE);
    float* sSq  = sSum + BLKN;

    const int tid = threadIdx.x, lane = tid & 31, warp = tid >> 5;
    const int wm = warp & 3, wn = warp >> 2;
    const int m0 = blockIdx.x * 128;
    const int n0 = blockIdx.y * BLKN;
    const uint32_t sb = smem_u32(smem);

    float acc[2][NFR][4];
#pragma unroll
    for (int i = 0; i < 2; i++)
#pragma unroll
        for (int j = 0; j < NFR; j++)
#pragma unroll
            for (int q = 0; q < 4; q++) acc[i][j][q] = 0.f;

    const int ra = lane & 15;
    const int ca = (lane & 16) ? 8 : 0;
    const int rb = (lane & 7) + ((lane & 16) ? 8 : 0);
    const int cb = (lane & 8) ? 8 : 0;

    auto load_stage = [&](int c, int st) {
        if (c >= NC) return;
        const int k0 = c * 32;
        const uint32_t base = sb + st * STAGE;
#pragma unroll
        for (int it = tid; it < 512; it += 256) {
            int r = it >> 2, q = it & 3;
            int gr = m0 + r;
            bool p = gr < M;
            int grc = p ? gr : 0;
            uint32_t so = (uint32_t)(r * LDS + q * 8) * 2;
            cp16(base + AH_OFF + so, Ahi + (size_t)grc * KK + k0 + q * 8, p);
            cp16(base + AL_OFF + so, Alo + (size_t)grc * KK + k0 + q * 8, p);
        }
#pragma unroll
        for (int it = tid; it < BLKN * 4; it += 256) {
            int r = it >> 2, q = it & 3;
            uint32_t so = (uint32_t)(r * LDS + q * 8) * 2;
            cp16(base + BH_OFF + so, Bhi + (size_t)(n0 + r) * KK + k0 + q * 8, true);
            cp16(base + BL_OFF + so, Blo + (size_t)(n0 + r) * KK + k0 + q * 8, true);
        }
    };

    load_stage(0, 0); CP_COMMIT();
    load_stage(1, 1); CP_COMMIT();

    for (int c = 0; c < NC; c++) {
        CP_WAIT1();
        __syncthreads();
        const int st = c & 1;
        const uint32_t base = sb + st * STAGE;
#pragma unroll
        for (int ks = 0; ks < 2; ks++) {
            const int kb = ks * 16;
            uint32_t ah[2][4], al[2][4], bh[NP][4], bl[NP][4];
#pragma unroll
            for (int mt = 0; mt < 2; mt++) {
                uint32_t off = (uint32_t)(((wm * 32 + mt * 16 + ra) * LDS + kb + ca) * 2);
                LDSM_X4(ah[mt][0], ah[mt][1], ah[mt][2], ah[mt][3], base + AH_OFF + off);
                LDSM_X4(al[mt][0], al[mt][1], al[mt][2], al[mt][3], base + AL_OFF + off);
            }
#pragma unroll
            for (int np = 0; np < NP; np++) {
                uint32_t off = (uint32_t)(((wn * WN + np * 16 + rb) * LDS + kb + cb) * 2);
                LDSM_X4(bh[np][0], bh[np][1], bh[np][2], bh[np][3], base + BH_OFF + off);
                LDSM_X4(bl[np][0], bl[np][1], bl[np][2], bl[np][3], base + BL_OFF + off);
            }
#pragma unroll
            for (int mt = 0; mt < 2; mt++)
#pragma unroll
                for (int nt = 0; nt < NFR; nt++) {
                    int np = nt >> 1, h = (nt & 1) * 2;
                    MMA_BF16(acc[mt][nt], ah[mt][0], ah[mt][1], ah[mt][2], ah[mt][3],
                             bh[np][h], bh[np][h + 1]);
                    MMA_BF16(acc[mt][nt], ah[mt][0], ah[mt][1], ah[mt][2], ah[mt][3],
                             bl[np][h], bl[np][h + 1]);
                    MMA_BF16(acc[mt][nt], al[mt][0], al[mt][1], al[mt][2], al[mt][3],
                             bh[np][h], bh[np][h + 1]);
                }
        }
        __syncthreads();
        load_stage(c + 2, st); CP_COMMIT();
    }

    // ---- epilogue ----
    if (STATS) {
        for (int t = tid; t < BLKN; t += 256) { sSum[t] = 0.f; sSq[t] = 0.f; }
        __syncthreads();
    }
    float a0 = 0.f;
    if (FUSEH) a0 = alpha[0] * (1.0f / 1.5f);

#pragma unroll
    for (int nt = 0; nt < NFR; nt++) {
        float s0 = 0.f, s1 = 0.f, q0 = 0.f, q1 = 0.f;
        const int col = n0 + wn * WN + nt * 8 + (lane & 3) * 2;
        const float bx = bias[col], by = bias[col + 1];
#pragma unroll
        for (int mt = 0; mt < 2; mt++) {
            int row = m0 + wm * 32 + mt * 16 + (lane >> 2);
            float v0 = acc[mt][nt][0] + bx, v1 = acc[mt][nt][1] + by;
            float v2 = acc[mt][nt][2] + bx, v3 = acc[mt][nt][3] + by;
            if (row < M) {
                *(float2*)(C + (size_t)row * ND + col) = make_float2(v0, v1);
                if (FUSEH) *(float2*)(outp + (size_t)row * ND + col) = make_float2(a0 * v0, a0 * v1);
                if (STATS) { s0 += v0; q0 += v0 * v0; s1 += v1; q1 += v1 * v1; }
            }
            if (row + 8 < M) {
                *(float2*)(C + (size_t)(row + 8) * ND + col) = make_float2(v2, v3);
                if (FUSEH) *(float2*)(outp + (size_t)(row + 8) * ND + col) = make_float2(a0 * v2, a0 * v3);
                if (STATS) { s0 += v2; q0 += v2 * v2; s1 += v3; q1 += v3 * v3; }
            }
        }
        if (STATS) {
#pragma unroll
            for (int m = 4; m < 32; m <<= 1) {
                s0 += __shfl_xor_sync(0xFFFFFFFFu, s0, m);
                s1 += __shfl_xor_sync(0xFFFFFFFFu, s1, m);
                q0 += __shfl_xor_sync(0xFFFFFFFFu, q0, m);
                q1 += __shfl_xor_sync(0xFFFFFFFFu, q1, m);
            }
            if (lane < 4) {
                int cl = wn * WN + nt * 8 + lane * 2;
                atomicAdd(&sSum[cl], s0);     atomicAdd(&sSum[cl + 1], s1);
                atomicAdd(&sSq[cl], q0);      atomicAdd(&sSq[cl + 1], q1);
            }
        }
    }
    if (STATS) {
        __syncthreads();
        for (int t = tid; t < BLKN; t += 256) {
            atomicAdd(&g_stats[n0 + t], sSum[t]);
            atomicAdd(&g_stats[HF + n0 + t], sSq[t]);
        }
    }
}

// ---------------- BN apply + GELU + bf16 split ----------------
__global__ void bn_apply_kernel(const float* __restrict__ pre,
                                const __nv_bfloat162* rhi, const __nv_bfloat162* rlo,
                                const float* __restrict__ gamma, const float* __restrict__ beta,
                                __nv_bfloat162* ohi, __nv_bfloat162* olo, int n) {
    size_t i = (size_t)blockIdx.x * blockDim.x + threadIdx.x;
    size_t total4 = (size_t)n * HF / 4;
    if (i >= total4) return;
    int f = (int)((i * 4) % HF);
    float4 p  = ((const float4*)pre)[i];
    float4 sm = *(const float4*)&g_stats[f];
    float4 sq = *(const float4*)&g_stats[HF + f];
    float4 gm = *(const float4*)&gamma[f];
    float4 bt = *(const float4*)&beta[f];
    const float invn = 1.0f / (float)n;
    float v0, v1, v2, v3;
    {
        float mean = sm.x * invn, var = sq.x * invn - mean * mean;
        v0 = gm.x * (p.x - mean) * rsqrtf(var + 1e-5f) + bt.x;
    }
    {
        float mean = sm.y * invn, var = sq.y * invn - mean * mean;
        v1 = gm.y * (p.y - mean) * rsqrtf(var + 1e-5f) + bt.y;
    }
    {
        float mean = sm.z * invn, var = sq.z * invn - mean * mean;
        v2 = gm.z * (p.z - mean) * rsqrtf(var + 1e-5f) + bt.z;
    }
    {
        float mean = sm.w * invn, var = sq.w * invn - mean * mean;
        v3 = gm.w * (p.w - mean) * rsqrtf(var + 1e-5f) + bt.w;
    }
    if (rhi) {
        __nv_bfloat162 h0 = rhi[i * 2], h1 = rhi[i * 2 + 1];
        __nv_bfloat162 l0 = rlo[i * 2], l1 = rlo[i * 2 + 1];
        v0 += __bfloat162float(h0.x) + __bfloat162float(l0.x);
        v1 += __bfloat162float(h0.y) + __bfloat162float(l0.y);
        v2 += __bfloat162float(h1.x) + __bfloat162float(l1.x);
        v3 += __bfloat162float(h1.y) + __bfloat162float(l1.y);
    }
    float o0 = gelu_exact(v0), o1 = gelu_exact(v1);
    float o2 = gelu_exact(v2), o3 = gelu_exact(v3);
    __nv_bfloat16 h0 = __float2bfloat16(o0), h1 = __float2bfloat16(o1);
    __nv_bfloat16 h2 = __float2bfloat16(o2), h3 = __float2bfloat16(o3);
    ohi[i * 2 + 0] = __nv_bfloat162(h0, h1);
    ohi[i * 2 + 1] = __nv_bfloat162(h2, h3);
    olo[i * 2 + 0] = __nv_bfloat162(__float2bfloat16(o0 - __bfloat162float(h0)),
                                    __float2bfloat16(o1 - __bfloat162float(h1)));
    olo[i * 2 + 1] = __nv_bfloat162(__float2bfloat16(o2 - __bfloat162float(h2)),
                                    __float2bfloat16(o3 - __bfloat162float(h3)));
}

// ---------------- propagation (int16-quantized, 1 warp/row) ----------------
__global__ void quant_kernel(const float2* __restrict__ src,
                             uint32_t* __restrict__ q, float* __restrict__ sc) {
    int r = (blockIdx.x * 256 + threadIdx.x) >> 5;
    int lane = threadIdx.x & 31;
    if (r >= NN) return;
    float2 v = src[(size_t)r * 32 + lane];
    float m = fmaxf(fabsf(v.x), fabsf(v.y));
#pragma unroll
    for (int o = 16; o; o >>= 1) m = fmaxf(m, __shfl_xor_sync(0xFFFFFFFFu, m, o));
    float inv = (m > 0.f) ? 32767.0f / m : 0.f;
    int qx = __float2int_rn(v.x * inv), qy = __float2int_rn(v.y * inv);
    q[(size_t)r * 32 + lane] = (uint32_t)(qx & 0xFFFF) | ((uint32_t)qy << 16);
    if (lane == 0) sc[r] = m * (1.0f / 32767.0f);
}

__global__ __launch_bounds__(256)
void prop_q_kernel(const uint32_t* __restrict__ qsrc, const float* __restrict__ ssrc,
                   uint32_t* __restrict__ qdst, float* __restrict__ sdst,
                   float2* __restrict__ acc, const float* __restrict__ alpha, int k) {
    int r = (blockIdx.x * 256 + threadIdx.x) >> 5;
    int lane = threadIdx.x & 31;
    if (r >= NN) return;
    int s = g_rowptr[r], e = g_rowptr[r + 1];
    float ax = 0.f, ay = 0.f;
    int i = s;
    for (; i + 4 <= e; i += 4) {
        int2 e0 = g_edge[i], e1 = g_edge[i + 1], e2 = g_edge[i + 2], e3 = g_edge[i + 3];
        float w0 = __int_as_float(e0.y) * ssrc[e0.x];
        float w1 = __int_as_float(e1.y) * ssrc[e1.x];
        float w2 = __int_as_float(e2.y) * ssrc[e2.x];
        float w3 = __int_as_float(e3.y) * ssrc[e3.x];
        uint32_t u0 = qsrc[(size_t)e0.x * 32 + lane];
        uint32_t u1 = qsrc[(size_t)e1.x * 32 + lane];
        uint32_t u2 = qsrc[(size_t)e2.x * 32 + lane];
        uint32_t u3 = qsrc[(size_t)e3.x * 32 + lane];
        ax += w0 * (float)((int)(short)(u0 & 0xFFFF)); ay += w0 * (float)(((int)u0) >> 16);
        ax += w1 * (float)((int)(short)(u1 & 0xFFFF)); ay += w1 * (float)(((int)u1) >> 16);
        ax += w2 * (float)((int)(short)(u2 & 0xFFFF)); ay += w2 * (float)(((int)u2) >> 16);
        ax += w3 * (float)((int)(short)(u3 & 0xFFFF)); ay += w3 * (float)(((int)u3) >> 16);
    }
    for (; i < e; i++) {
        int2 ed = g_edge[i];
        float w = __int_as_float(ed.y) * ssrc[ed.x];
        uint32_t u = qsrc[(size_t)ed.x * 32 + lane];
        ax += w * (float)((int)(short)(u & 0xFFFF));
        ay += w * (float)(((int)u) >> 16);
    }
    // quantize new hop
    float m = fmaxf(fabsf(ax), fabsf(ay));
#pragma unroll
    for (int o = 16; o; o >>= 1) m = fmaxf(m, __shfl_xor_sync(0xFFFFFFFFu, m, o));
    float inv = (m > 0.f) ? 32767.0f / m : 0.f;
    int qx = __float2int_rn(ax * inv), qy = __float2int_rn(ay * inv);
    qdst[(size_t)r * 32 + lane] = (uint32_t)(qx & 0xFFFF) | ((uint32_t)qy << 16);
    if (lane == 0) sdst[r] = m * (1.0f / 32767.0f);
    // accumulate (uses pre-quantization fp32 values)
    float aa = alpha[k] * (1.0f / 1.5f);
    size_t o = (size_t)r * 32 + lane;
    float2 ac = acc[o];
    ac.x += aa * ax; ac.y += aa * ay;
    acc[o] = ac;
}

// ---------------- launch ----------------
extern "C" void kernel_launch(void* const* d_in, const int* in_sizes, int n_in,
                              void* d_out, int out_size) {
    const float* x  = (const float*)d_in[0];
    const int*   ei = (const int*)d_in[1];
    const float *w1 = (const float*)d_in[2],  *b1 = (const float*)d_in[3];
    const float *ga1 = (const float*)d_in[4], *be1 = (const float*)d_in[5];
    const float *w2 = (const float*)d_in[6],  *b2 = (const float*)d_in[7];
    const float *ga2 = (const float*)d_in[8], *be2 = (const float*)d_in[9];
    const float *w3 = (const float*)d_in[10], *b3 = (const float*)d_in[11];
    const float *ga3 = (const float*)d_in[12], *be3 = (const float*)d_in[13];
    const float *w4 = (const float*)d_in[14], *b4 = (const float*)d_in[15];
    const float *alpha = (const float*)d_in[16];
    float* out = (float*)d_out;

    const int* rowp = ei;
    const int* colp = ei + EE;

    float *bufA, *hbuf, *stats, *sc1, *sc2;
    uint32_t *q1, *q2;
    __nv_bfloat16 *ahi, *alo, *w1h, *w1l, *w2h, *w2l, *w3h, *w3l, *w4h, *w4l;
    cudaGetSymbolAddress((void**)&bufA, g_bufA);
    cudaGetSymbolAddress((void**)&hbuf, g_h);
    cudaGetSymbolAddress((void**)&stats, g_stats);
    cudaGetSymbolAddress((void**)&q1, g_q1);
    cudaGetSymbolAddress((void**)&q2, g_q2);
    cudaGetSymbolAddress((void**)&sc1, g_sc1);
    cudaGetSymbolAddress((void**)&sc2, g_sc2);
    cudaGetSymbolAddress((void**)&ahi, g_ahi);
    cudaGetSymbolAddress((void**)&alo, g_alo);
    cudaGetSymbolAddress((void**)&w1h, g_w1hi); cudaGetSymbolAddress((void**)&w1l, g_w1lo);
    cudaGetSymbolAddress((void**)&w2h, g_w2hi); cudaGetSymbolAddress((void**)&w2l, g_w2lo);
    cudaGetSymbolAddress((void**)&w3h, g_w3hi); cudaGetSymbolAddress((void**)&w3l, g_w3lo);
    cudaGetSymbolAddress((void**)&w4h, g_w4hi); cudaGetSymbolAddress((void**)&w4l, g_w4lo);

    constexpr int LDS = 40;
    const int STAGE_N = (2 * 128 + 2 * 128) * LDS * 2;   // BLKN=128: 40960
    const int SMEM_N  = 2 * STAGE_N + 2 * 128 * (int)sizeof(float);
    const int STAGE_S = (2 * 128 + 2 * 64) * LDS * 2;    // BLKN=64: 30720
    const int SMEM_S  = 2 * STAGE_S + 2 * 64 * (int)sizeof(float);
    cudaFuncSetAttribute(hmma_gemm_kernel<HF, 128, INF, true, false>,
                         cudaFuncAttributeMaxDynamicSharedMemorySize, SMEM_N);
    cudaFuncSetAttribute(hmma_gemm_kernel<HF, 128, HF, true, false>,
                         cudaFuncAttributeMaxDynamicSharedMemorySize, SMEM_N);
    cudaFuncSetAttribute(hmma_gemm_kernel<OUTF, 64, HF, false, true>,
                         cudaFuncAttributeMaxDynamicSharedMemorySize, SMEM_S);

    // --- graph preprocessing ---
    init_kernel<<<(NN + 255) / 256, 256>>>();
    degree_kernel<<<(EE + 255) / 256, 256>>>(rowp);
    dinv_kernel<<<(NN + 255) / 256, 256>>>();
    const int nsb = (NN + 255) / 256;
    scan1_kernel<<<nsb, 256>>>();
    scan2_kernel<<<1, 512>>>(nsb);
    scan3_kernel<<<nsb, 256>>>();
    scatter_kernel<<<(TOTE + 255) / 256, 256>>>(rowp, colp);

    // --- operand conversions ---
    split2_kernel<<<(int)(((size_t)NN * INF / 2 + 255) / 256), 256>>>(
        x, (__nv_bfloat162*)ahi, (__nv_bfloat162*)alo, (size_t)NN * INF / 2);
    wsplit_kernel<<<(INF * HF + 255) / 256, 256>>>(w1, w1h, w1l, INF, HF);
    wsplit_kernel<<<(HF * HF + 255) / 256, 256>>>(w2, w2h, w2l, HF, HF);
    wsplit_kernel<<<(HF * HF + 255) / 256, 256>>>(w3, w3h, w3l, HF, HF);
    wsplit_kernel<<<(HF * OUTF + 255) / 256, 256>>>(w4, w4h, w4l, HF, OUTF);

    const int gx = (NN + 127) / 128;   // 782
    const int elem4 = (int)(((size_t)NN * HF / 4 + 255) / 256);

    // layer 1
    cudaMemsetAsync(stats, 0, 2 * HF * sizeof(float));
    hmma_gemm_kernel<HF, 128, INF, true, false><<<dim3(gx, 2), 256, SMEM_N>>>(
        ahi, alo, w1h, w1l, b1, bufA, NN, nullptr, nullptr);
    bn_apply_kernel<<<elem4, 256>>>(bufA, nullptr, nullptr, ga1, be1,
                                    (__nv_bfloat162*)ahi, (__nv_bfloat162*)alo, NN);
    // layer 2
    cudaMemsetAsync(stats, 0, 2 * HF * sizeof(float));
    hmma_gemm_kernel<HF, 128, HF, true, false><<<dim3(gx, 2), 256, SMEM_N>>>(
        ahi, alo, w2h, w2l, b2, bufA, NN, nullptr, nullptr);
    bn_apply_kernel<<<elem4, 256>>>(bufA, (__nv_bfloat162*)ahi, (__nv_bfloat162*)alo, ga2, be2,
                                    (__nv_bfloat162*)ahi, (__nv_bfloat162*)alo, NN);
    // layer 3
    cudaMemsetAsync(stats, 0, 2 * HF * sizeof(float));
    hmma_gemm_kernel<HF, 128, HF, true, false><<<dim3(gx, 2), 256, SMEM_N>>>(
        ahi, alo, w3h, w3l, b3, bufA, NN, nullptr, nullptr);
    bn_apply_kernel<<<elem4, 256>>>(bufA, (__nv_bfloat162*)ahi, (__nv_bfloat162*)alo, ga3, be3,
                                    (__nv_bfloat162*)ahi, (__nv_bfloat162*)alo, NN);
    // layer 4 (+ fused prop-init: out = alpha0/1.5 * h)
    hmma_gemm_kernel<OUTF, 64, HF, false, true><<<dim3(gx, 1), 256, SMEM_S>>>(
        ahi, alo, w4h, w4l, b4, hbuf, NN, out, alpha);

    // --- propagation (quantized) ---
    quant_kernel<<<(NN * 32 + 255) / 256, 256>>>((const float2*)hbuf, q1, sc1);
    uint32_t* qs[2] = { q1, q2 };
    float*    ss[2] = { sc1, sc2 };
    for (int k = 1; k <= 10; k++) {
        int a = (k - 1) & 1, b = k & 1;
        prop_q_kernel<<<(NN * 32 + 255) / 256, 256>>>(
            qs[a], ss[a], qs[b], ss[b], (float2*)out, alpha, k);
    }
}